// round 2
// baseline (speedup 1.0000x reference)
#include <cuda_runtime.h>
#include <math.h>
#include <stdint.h>

// ---------------------------------------------------------------------------
// tcnn HashGrid encode: coords [N,3] in [0,1], table [16, 2^19, 2] f32.
// Output [N, 32] f32 (16 levels x 2 feats, trilinear).
// Levels 0-4 dense (res^3 <= 2^19), levels 5-15 spatial-hashed.
//
// Key idea this round: dense levels are L1-wavefront-bound on 8 scattered
// 8B corner gathers. Repack each dense cell's 8 corners into one contiguous
// 64B record (static __device__ scratch); 4 lanes then fetch a point's whole
// cell with 4x LDG.128 hitting ONE 128B line -> ~1 wavefront/point instead
// of 8. Hashed levels keep the lane=point layout (irreducibly random).
// ---------------------------------------------------------------------------

namespace {
constexpr int      NLV    = 16;
constexpr int      NDENSE = 5;    // levels 0..4 dense
constexpr int      NHASH  = 11;   // levels 5..15 hashed
constexpr unsigned TSZ    = 1u << 19;
constexpr unsigned TMASK  = TSZ - 1u;
constexpr unsigned PRIME2 = 2654435761u;
constexpr unsigned PRIME3 = 805459861u;
// actual dense cell total = 16^3+24^3+34^3+49^3+71^3 = 532784; margin for safety
constexpr int      MAX_CELLS = 540000;
}

struct LevelMeta {
    float    scale;   // base * s^l - 1
    unsigned res;     // ceil(scale) + 1
    unsigned res2;    // res*res
    unsigned hashed;  // res^3 > T ?
};

__device__ LevelMeta g_meta[NLV];
__device__ unsigned  g_cell_off[NDENSE + 1];           // [NDENSE] = total cells
__device__ __align__(128) float4 g_cells[(size_t)MAX_CELLS * 4];  // 64B per cell

// --- per-level constants in fp64 (matches Python pow/ceil); 1 thread, ~free.
__global__ void hg_init_meta() {
    if (threadIdx.x == 0) {
        unsigned off = 0;
        for (int l = 0; l < NLV; ++l) {
            double sc = 16.0 * pow(1.4472692012786865, (double)l) - 1.0;
            unsigned res = (unsigned)ceil(sc) + 1u;
            unsigned long long r3 = (unsigned long long)res * res * res;
            LevelMeta m;
            m.scale  = (float)sc;
            m.res    = res;
            m.res2   = res * res;
            m.hashed = (r3 > (unsigned long long)TSZ) ? 1u : 0u;
            g_meta[l] = m;
            if (l < NDENSE) { g_cell_off[l] = off; off += (unsigned)r3; }
        }
        g_cell_off[NDENSE] = off;
    }
}

// --- repack dense levels: cell (gx,gy,gz) -> 4 float4 = 8 corners (64B).
// chunk k holds corners (dx=k>>1, dy=k&1, dz=0 in .xy, dz=1 in .zw).
__global__ void hg_repack(const float2* __restrict__ table) {
    const unsigned total = g_cell_off[NDENSE];
    unsigned cid = blockIdx.x * blockDim.x + threadIdx.x;
    if (cid >= total) return;

    int l = 0;
    while (l + 1 < NDENSE && cid >= g_cell_off[l + 1]) ++l;
    const LevelMeta m = g_meta[l];
    const unsigned local = cid - g_cell_off[l];
    const unsigned gz  = local / m.res2;
    const unsigned rem = local - gz * m.res2;
    const unsigned gy  = rem / m.res;
    const unsigned gx  = rem - gy * m.res;

    const unsigned R1  = m.res - 1u;
    const unsigned cx0 = gx,               cx1 = min(gx + 1u, R1);
    const unsigned cy0 = gy * m.res,       cy1 = min(gy + 1u, R1) * m.res;
    const unsigned cz0 = gz * m.res2,      cz1 = min(gz + 1u, R1) * m.res2;

    const float2* __restrict__ tbl = table + (size_t)l * (size_t)TSZ;
    float4* dst = &g_cells[(size_t)cid * 4];

    { float2 a = tbl[cx0 + cy0 + cz0], b = tbl[cx0 + cy0 + cz1];
      dst[0] = make_float4(a.x, a.y, b.x, b.y); }         // (0,0)
    { float2 a = tbl[cx0 + cy1 + cz0], b = tbl[cx0 + cy1 + cz1];
      dst[1] = make_float4(a.x, a.y, b.x, b.y); }         // (0,1)
    { float2 a = tbl[cx1 + cy0 + cz0], b = tbl[cx1 + cy0 + cz1];
      dst[2] = make_float4(a.x, a.y, b.x, b.y); }         // (1,0)
    { float2 a = tbl[cx1 + cy1 + cz0], b = tbl[cx1 + cy1 + cz1];
      dst[3] = make_float4(a.x, a.y, b.x, b.y); }         // (1,1)
}

// --- main encode. Block = 992 threads = 31 warps, 32 points per block.
// warps 0..10 : hashed levels 5..15, lane = point (warp-coherent, MLP=8).
// warps 11..30: dense levels, 4 lanes per point fetch one 64B cell record
//               (same 128B line) and butterfly-reduce partials.
__global__ __launch_bounds__(992) void hg_encode(
    const float*  __restrict__ coords,
    const float2* __restrict__ table,
    float*        __restrict__ out,
    int n_points)
{
    __shared__ float s_c[96];         // 32 points x 3 coords
    __shared__ float s_out[32][33];   // [point][feat], padded

    const int tid   = threadIdx.x;
    const int lane  = tid & 31;
    const int warp  = tid >> 5;
    const int pbase = blockIdx.x * 32;

    if (tid < 96) {
        const int g = pbase * 3 + tid;
        s_c[tid] = (g < n_points * 3) ? coords[g] : 0.0f;   // OOB -> 0 (safe coords)
    }
    __syncthreads();

    if (warp < NHASH) {
        // ------- hashed levels -------
        const int level = warp + NDENSE;
        const int p     = pbase + lane;

        const float x = s_c[lane * 3 + 0];
        const float y = s_c[lane * 3 + 1];
        const float z = s_c[lane * 3 + 2];
        const LevelMeta m = g_meta[level];

        const float px = x * m.scale + 0.5f;
        const float py = y * m.scale + 0.5f;
        const float pz = z * m.scale + 0.5f;
        const float fx = floorf(px), fy = floorf(py), fz = floorf(pz);
        const float wx = px - fx,    wy = py - fy,    wz = pz - fz;
        const unsigned gx = (unsigned)fx, gy = (unsigned)fy, gz = (unsigned)fz;

        const unsigned hx0 = gx,          hx1 = gx + 1u;
        const unsigned hy0 = gy * PRIME2, hy1 = hy0 + PRIME2;
        const unsigned hz0 = gz * PRIME3, hz1 = hz0 + PRIME3;
        const unsigned i0 = (hx0 ^ hy0 ^ hz0) & TMASK;
        const unsigned i1 = (hx0 ^ hy0 ^ hz1) & TMASK;
        const unsigned i2 = (hx0 ^ hy1 ^ hz0) & TMASK;
        const unsigned i3 = (hx0 ^ hy1 ^ hz1) & TMASK;
        const unsigned i4 = (hx1 ^ hy0 ^ hz0) & TMASK;
        const unsigned i5 = (hx1 ^ hy0 ^ hz1) & TMASK;
        const unsigned i6 = (hx1 ^ hy1 ^ hz0) & TMASK;
        const unsigned i7 = (hx1 ^ hy1 ^ hz1) & TMASK;

        const float2* __restrict__ tbl = table + (size_t)level * (size_t)TSZ;
        const float2 v0 = __ldg(tbl + i0);
        const float2 v1 = __ldg(tbl + i1);
        const float2 v2 = __ldg(tbl + i2);
        const float2 v3 = __ldg(tbl + i3);
        const float2 v4 = __ldg(tbl + i4);
        const float2 v5 = __ldg(tbl + i5);
        const float2 v6 = __ldg(tbl + i6);
        const float2 v7 = __ldg(tbl + i7);

        const float ix = 1.0f - wx, iy = 1.0f - wy, iz = 1.0f - wz;
        const float a00 = ix * iy, a01 = ix * wy, a10 = wx * iy, a11 = wx * wy;
        const float w0 = a00 * iz, w1 = a00 * wz;
        const float w2 = a01 * iz, w3 = a01 * wz;
        const float w4 = a10 * iz, w5 = a10 * wz;
        const float w6 = a11 * iz, w7 = a11 * wz;

        float f0 = w0 * v0.x;  float f1 = w0 * v0.y;
        f0 += w1 * v1.x;       f1 += w1 * v1.y;
        f0 += w2 * v2.x;       f1 += w2 * v2.y;
        f0 += w3 * v3.x;       f1 += w3 * v3.y;
        f0 += w4 * v4.x;       f1 += w4 * v4.y;
        f0 += w5 * v5.x;       f1 += w5 * v5.y;
        f0 += w6 * v6.x;       f1 += w6 * v6.y;
        f0 += w7 * v7.x;       f1 += w7 * v7.y;

        if (p < n_points) {
            s_out[lane][2 * level + 0] = f0;
            s_out[lane][2 * level + 1] = f1;
        }
    } else {
        // ------- dense levels: quad-lane cell fetch -------
        const int w     = warp - NHASH;   // 0..19
        const int level = w >> 2;         // 0..4
        const int sub   = w & 3;          // point subgroup
        const int q     = lane >> 2;      // 0..7
        const int k     = lane & 3;       // chunk / corner pair id
        const int pt    = sub * 8 + q;    // 0..31
        const int p     = pbase + pt;

        const float x = s_c[pt * 3 + 0];
        const float y = s_c[pt * 3 + 1];
        const float z = s_c[pt * 3 + 2];
        const LevelMeta m = g_meta[level];

        const float px = x * m.scale + 0.5f;
        const float py = y * m.scale + 0.5f;
        const float pz = z * m.scale + 0.5f;
        const float fx = floorf(px), fy = floorf(py), fz = floorf(pz);
        const float wx = px - fx,    wy = py - fy,    wz = pz - fz;
        const unsigned gx = (unsigned)fx, gy = (unsigned)fy, gz = (unsigned)fz;

        const unsigned cell = g_cell_off[level] + gx + gy * m.res + gz * m.res2;
        const float4 ch = __ldg(&g_cells[(size_t)cell * 4 + k]);  // 4 lanes, 1 line

        const float wdx = (k & 2) ? wx : 1.0f - wx;
        const float wdy = (k & 1) ? wy : 1.0f - wy;
        const float iz  = 1.0f - wz;
        const float s   = wdx * wdy;
        float f0 = s * (iz * ch.x + wz * ch.z);
        float f1 = s * (iz * ch.y + wz * ch.w);

        // sum 4 chunk partials within the quad
        f0 += __shfl_xor_sync(0xffffffffu, f0, 1);
        f1 += __shfl_xor_sync(0xffffffffu, f1, 1);
        f0 += __shfl_xor_sync(0xffffffffu, f0, 2);
        f1 += __shfl_xor_sync(0xffffffffu, f1, 2);

        if (k == 0 && p < n_points) {
            s_out[pt][2 * level + 0] = f0;
            s_out[pt][2 * level + 1] = f1;
        }
    }
    __syncthreads();

    // Coalesced writeback: 512 threads x float2 = 4KB contiguous per block.
    if (tid < 512) {
        const int pp = tid >> 4;
        const int c  = (tid & 15) * 2;
        const int gp = pbase + pp;
        if (gp < n_points) {
            const float a = s_out[pp][c];
            const float b = s_out[pp][c + 1];
            float2* o = reinterpret_cast<float2*>(out + (size_t)gp * 32 + c);
            *o = make_float2(a, b);
        }
    }
}

extern "C" void kernel_launch(void* const* d_in, const int* in_sizes, int n_in,
                              void* d_out, int out_size) {
    const float*  coords = (const float*)d_in[0];   // [N, 3] f32
    const float2* table  = (const float2*)d_in[1];  // [16, 2^19, 2] f32
    float*        out    = (float*)d_out;           // [N, 32] f32
    const int n_points = in_sizes[0] / 3;

    hg_init_meta<<<1, 1>>>();
    hg_repack<<<(MAX_CELLS + 255) / 256, 256>>>(table);
    const int blocks = (n_points + 31) / 32;
    hg_encode<<<blocks, 992>>>(coords, table, out, n_points);
}

// round 3
// speedup vs baseline: 1.2600x; 1.2600x over previous
#include <cuda_runtime.h>
#include <stdint.h>

// ---------------------------------------------------------------------------
// tcnn HashGrid encode: coords [N,3] in [0,1], table [16, 2^19, 2] f32.
// Output [N, 32] f32. Levels 0-4 dense, 5-15 spatial-hashed.
//
// R3: (a) compile-time level constants (no init kernel; R2's cost 49us),
//     (b) hashed x-pair merge: PRIME_x==1 -> for even gx the two x-corners
//         are adjacent table entries -> one LDG.128 replaces two LDG.64
//         (~25% fewer L1 wavefronts on the dominant hashed gathers),
//     (c) dense levels via repacked 64B cell records + quad-lane LDG.128
//         (1 wavefront/point/level instead of 8).
// ---------------------------------------------------------------------------

namespace {
constexpr int      NLV    = 16;
constexpr int      NDENSE = 5;
constexpr int      NHASH  = 11;
constexpr unsigned TSZ    = 1u << 19;
constexpr unsigned TMASK  = TSZ - 1u;
constexpr unsigned PRIME2 = 2654435761u;
constexpr unsigned PRIME3 = 805459861u;

constexpr double spow(int l) {
    double v = 1.0;
    for (int i = 0; i < l; ++i) v *= 1.4472692012786865;
    return v;
}
constexpr double scaled(int l) { return 16.0 * spow(l) - 1.0; }
constexpr unsigned resd(int l) {
    double sc = scaled(l);
    unsigned f = (unsigned)sc;
    return f + (((double)f < sc) ? 1u : 0u) + 1u;
}
constexpr unsigned cells_below(int l) {
    unsigned o = 0;
    for (int i = 0; i < l; ++i) o += resd(i) * resd(i) * resd(i);
    return o;
}
constexpr unsigned TOTAL_CELLS = cells_below(NDENSE);
static_assert(resd(0) == 16 && resd(4) == 71, "dense res sanity");
static_assert((unsigned long long)resd(4)*resd(4)*resd(4) <= TSZ, "lvl4 dense");
static_assert((unsigned long long)resd(5)*resd(5)*resd(5) >  TSZ, "lvl5 hashed");
static_assert(TOTAL_CELLS == 532784u, "cell count");
}

__constant__ float    c_scale[NLV] = {
    (float)scaled(0),(float)scaled(1),(float)scaled(2),(float)scaled(3),
    (float)scaled(4),(float)scaled(5),(float)scaled(6),(float)scaled(7),
    (float)scaled(8),(float)scaled(9),(float)scaled(10),(float)scaled(11),
    (float)scaled(12),(float)scaled(13),(float)scaled(14),(float)scaled(15)};
__constant__ unsigned c_res[NDENSE]  = {resd(0),resd(1),resd(2),resd(3),resd(4)};
__constant__ unsigned c_res2[NDENSE] = {resd(0)*resd(0),resd(1)*resd(1),
    resd(2)*resd(2),resd(3)*resd(3),resd(4)*resd(4)};
__constant__ unsigned c_coff[NDENSE] = {cells_below(0),cells_below(1),
    cells_below(2),cells_below(3),cells_below(4)};

__device__ __align__(128) float4 g_cells[(size_t)TOTAL_CELLS * 4];

// --- repack dense levels: cell (gx,gy,gz) -> 4 float4 = 8 corners (64B).
// chunk k: dx=k>>1, dy=k&1; dz=0 in .xy, dz=1 in .zw.
__global__ void hg_repack(const float2* __restrict__ table) {
    unsigned cid = blockIdx.x * blockDim.x + threadIdx.x;
    if (cid >= TOTAL_CELLS) return;

    int l = 0;
    #pragma unroll
    for (int i = 1; i < NDENSE; ++i) if (cid >= c_coff[i]) l = i;
    const unsigned res = c_res[l], res2 = c_res2[l];
    const unsigned local = cid - c_coff[l];
    const unsigned gz  = local / res2;
    const unsigned rem = local - gz * res2;
    const unsigned gy  = rem / res;
    const unsigned gx  = rem - gy * res;

    const unsigned R1  = res - 1u;
    const unsigned cx0 = gx,          cx1 = min(gx + 1u, R1);
    const unsigned cy0 = gy * res,    cy1 = min(gy + 1u, R1) * res;
    const unsigned cz0 = gz * res2,   cz1 = min(gz + 1u, R1) * res2;

    const float2* __restrict__ tbl = table + (size_t)l * (size_t)TSZ;
    float4* dst = &g_cells[(size_t)cid * 4];
    { float2 a = tbl[cx0+cy0+cz0], b = tbl[cx0+cy0+cz1]; dst[0]=make_float4(a.x,a.y,b.x,b.y); }
    { float2 a = tbl[cx0+cy1+cz0], b = tbl[cx0+cy1+cz1]; dst[1]=make_float4(a.x,a.y,b.x,b.y); }
    { float2 a = tbl[cx1+cy0+cz0], b = tbl[cx1+cy0+cz1]; dst[2]=make_float4(a.x,a.y,b.x,b.y); }
    { float2 a = tbl[cx1+cy1+cz0], b = tbl[cx1+cy1+cz1]; dst[3]=make_float4(a.x,a.y,b.x,b.y); }
}

// --- main encode. Block = 512 threads = 16 warps, 32 points per block.
// warps 0..10 : hashed level (warp+5), lane = point.
// warps 11..15: dense level (warp-11), quad-lane cell fetch, 4 subgroups.
__global__ __launch_bounds__(512, 3) void hg_encode(
    const float*  __restrict__ coords,
    const float2* __restrict__ table,
    float*        __restrict__ out,
    int n_points)
{
    __shared__ float s_c[96];         // 32 points x 3 coords
    __shared__ float s_out[32][33];   // [point][feat], padded

    const int tid   = threadIdx.x;
    const int lane  = tid & 31;
    const int warp  = tid >> 5;
    const int pbase = blockIdx.x * 32;

    if (tid < 96) {
        const int g = pbase * 3 + tid;
        s_c[tid] = (g < n_points * 3) ? coords[g] : 0.0f;
    }
    __syncthreads();

    if (warp < NHASH) {
        // ---------------- hashed levels ----------------
        const int level = warp + NDENSE;
        const float x = s_c[lane*3+0], y = s_c[lane*3+1], z = s_c[lane*3+2];
        const float sc = c_scale[level];

        const float px = x*sc + 0.5f, py = y*sc + 0.5f, pz = z*sc + 0.5f;
        const float fx = floorf(px), fy = floorf(py), fz = floorf(pz);
        const float wx = px - fx,    wy = py - fy,    wz = pz - fz;
        const unsigned gx = (unsigned)fx, gy = (unsigned)fy, gz = (unsigned)fz;

        const unsigned hy0 = gy * PRIME2, hy1 = hy0 + PRIME2;
        const unsigned hz0 = gz * PRIME3, hz1 = hz0 + PRIME3;
        // j = (dy,dz): 0=(0,0) 1=(0,1) 2=(1,0) 3=(1,1); dx=0 -> v[j], dx=1 -> v[4+j]
        unsigned e[4];
        e[0] = (gx ^ hy0 ^ hz0) & TMASK;
        e[1] = (gx ^ hy0 ^ hz1) & TMASK;
        e[2] = (gx ^ hy1 ^ hz0) & TMASK;
        e[3] = (gx ^ hy1 ^ hz1) & TMASK;

        const float2* __restrict__ tbl = table + (size_t)level * (size_t)TSZ;
        float2 v[8];
        if (!(gx & 1u)) {
            // even gx: x-corner pair = entries {e&~1, e|1} -> one 16B load
            #pragma unroll
            for (int j = 0; j < 4; ++j) {
                const float4 q = __ldg(reinterpret_cast<const float4*>(tbl + (e[j] & ~1u)));
                const bool hi = (e[j] & 1u);
                v[j]     = hi ? make_float2(q.z, q.w) : make_float2(q.x, q.y);
                v[4 + j] = hi ? make_float2(q.x, q.y) : make_float2(q.z, q.w);
            }
        } else {
            const unsigned gx1 = gx + 1u;
            unsigned f[4];
            f[0] = (gx1 ^ hy0 ^ hz0) & TMASK;
            f[1] = (gx1 ^ hy0 ^ hz1) & TMASK;
            f[2] = (gx1 ^ hy1 ^ hz0) & TMASK;
            f[3] = (gx1 ^ hy1 ^ hz1) & TMASK;
            #pragma unroll
            for (int j = 0; j < 4; ++j) v[j]     = __ldg(tbl + e[j]);
            #pragma unroll
            for (int j = 0; j < 4; ++j) v[4 + j] = __ldg(tbl + f[j]);
        }

        const float ix = 1.0f - wx, iy = 1.0f - wy, iz = 1.0f - wz;
        const float a00 = ix*iy, a01 = ix*wy, a10 = wx*iy, a11 = wx*wy;
        const float w0 = a00*iz, w1 = a00*wz, w2 = a01*iz, w3 = a01*wz;
        const float w4 = a10*iz, w5 = a10*wz, w6 = a11*iz, w7 = a11*wz;

        float f0 = w0*v[0].x;  float f1 = w0*v[0].y;
        f0 += w1*v[1].x;       f1 += w1*v[1].y;
        f0 += w2*v[2].x;       f1 += w2*v[2].y;
        f0 += w3*v[3].x;       f1 += w3*v[3].y;
        f0 += w4*v[4].x;       f1 += w4*v[4].y;
        f0 += w5*v[5].x;       f1 += w5*v[5].y;
        f0 += w6*v[6].x;       f1 += w6*v[6].y;
        f0 += w7*v[7].x;       f1 += w7*v[7].y;

        s_out[lane][2*level + 0] = f0;
        s_out[lane][2*level + 1] = f1;
    } else {
        // ---------------- dense levels: quad-lane cell fetch ----------------
        const int level = warp - NHASH;           // 0..4
        const float    sc   = c_scale[level];
        const unsigned res  = c_res[level];
        const unsigned res2 = c_res2[level];
        const unsigned coff = c_coff[level];
        const int q = lane >> 2;                  // 0..7 point-in-subgroup
        const int k = lane & 3;                   // chunk: dx=k>>1, dy=k&1

        #pragma unroll
        for (int it = 0; it < 4; ++it) {
            const int pt = it * 8 + q;            // 0..31
            const float x = s_c[pt*3+0], y = s_c[pt*3+1], z = s_c[pt*3+2];
            const float px = x*sc + 0.5f, py = y*sc + 0.5f, pz = z*sc + 0.5f;
            const float fx = floorf(px), fy = floorf(py), fz = floorf(pz);
            const float wx = px - fx,    wy = py - fy,    wz = pz - fz;
            const unsigned gx = (unsigned)fx, gy = (unsigned)fy, gz = (unsigned)fz;

            const unsigned cell = coff + gx + gy*res + gz*res2;
            const float4 ch = __ldg(&g_cells[(size_t)cell * 4 + k]);  // 4 lanes: 1 line

            const float wdx = (k & 2) ? wx : 1.0f - wx;
            const float wdy = (k & 1) ? wy : 1.0f - wy;
            const float izz = 1.0f - wz;
            const float s   = wdx * wdy;
            float f0 = s * (izz*ch.x + wz*ch.z);
            float f1 = s * (izz*ch.y + wz*ch.w);

            f0 += __shfl_xor_sync(0xffffffffu, f0, 1);
            f1 += __shfl_xor_sync(0xffffffffu, f1, 1);
            f0 += __shfl_xor_sync(0xffffffffu, f0, 2);
            f1 += __shfl_xor_sync(0xffffffffu, f1, 2);

            if (k == 0) {
                s_out[pt][2*level + 0] = f0;
                s_out[pt][2*level + 1] = f1;
            }
        }
    }
    __syncthreads();

    // Coalesced writeback: 512 threads x float2 = 4KB contiguous per block.
    const int pp = tid >> 4;
    const int c  = (tid & 15) * 2;
    const int gp = pbase + pp;
    if (gp < n_points) {
        const float a = s_out[pp][c];
        const float b = s_out[pp][c + 1];
        float2* o = reinterpret_cast<float2*>(out + (size_t)gp * 32 + c);
        *o = make_float2(a, b);
    }
}

extern "C" void kernel_launch(void* const* d_in, const int* in_sizes, int n_in,
                              void* d_out, int out_size) {
    const float*  coords = (const float*)d_in[0];   // [N, 3] f32
    const float2* table  = (const float2*)d_in[1];  // [16, 2^19, 2] f32
    float*        out    = (float*)d_out;           // [N, 32] f32
    const int n_points = in_sizes[0] / 3;

    hg_repack<<<(TOTAL_CELLS + 255) / 256, 256>>>(table);
    const int blocks = (n_points + 31) / 32;
    hg_encode<<<blocks, 512>>>(coords, table, out, n_points);
}